// round 8
// baseline (speedup 1.0000x reference)
#include <cuda_runtime.h>
#include <cuda_fp16.h>

// SNN: B=4096, T=256, I=7, H=64, O=8
// R7: 2 warps per batch (h split), 1 hidden unit per lane -> 8192 warps,
// ~55 warps/SM for latency hiding. Recurrence fp32; outputs per 32-step
// chunk via HMMA m16n8k16 split by m-tile across the warp pair.

#define THRESH 1.0f
#define BETA 0.8f

typedef unsigned long long u64;
typedef unsigned int u32;

constexpr int T_ = 256;
constexpr int I_ = 7;
constexpr int H_ = 64;
constexpr int O_ = 8;
constexpr int TCHUNK = 32;
constexpr int SPK_STRIDE = 72;   // halves per spike row (64 + 8 pad) = 144B

__device__ __forceinline__ u64 pack2(float lo, float hi) {
    u64 r; asm("mov.b64 %0, {%1, %2};" : "=l"(r) : "f"(lo), "f"(hi)); return r;
}
__device__ __forceinline__ void unpack2(u64 v, float& lo, float& hi) {
    asm("mov.b64 {%0, %1}, %2;" : "=f"(lo), "=f"(hi) : "l"(v));
}
__device__ __forceinline__ u64 fma2(u64 a, u64 b, u64 c) {
    u64 d; asm("fma.rn.f32x2 %0, %1, %2, %3;" : "=l"(d) : "l"(a), "l"(b), "l"(c)); return d;
}
__device__ __forceinline__ void ldsm_x4(u32& r0, u32& r1, u32& r2, u32& r3, u32 addr) {
    asm volatile("ldmatrix.sync.aligned.m8n8.x4.shared.b16 {%0,%1,%2,%3}, [%4];"
                 : "=r"(r0), "=r"(r1), "=r"(r2), "=r"(r3) : "r"(addr));
}
__device__ __forceinline__ void mma16816(float& c0, float& c1, float& c2, float& c3,
                                         u32 a0, u32 a1, u32 a2, u32 a3,
                                         u32 b0, u32 b1) {
    asm volatile("mma.sync.aligned.m16n8k16.row.col.f32.f16.f16.f32 "
                 "{%0,%1,%2,%3},{%4,%5,%6,%7},{%8,%9},{%0,%1,%2,%3};"
                 : "+f"(c0), "+f"(c1), "+f"(c2), "+f"(c3)
                 : "r"(a0), "r"(a1), "r"(a2), "r"(a3), "r"(b0), "r"(b1));
}

__global__ __launch_bounds__(128, 12)
void snn_kernel(const float* __restrict__ x,
                const float* __restrict__ hs,
                const float* __restrict__ W1,
                const float* __restrict__ b1,
                const float* __restrict__ W2,
                const float* __restrict__ b2,
                float* __restrict__ out,     // (B,T,8)
                float* __restrict__ newh,    // (B,T,64)
                int B)
{
    // Per block: 2 batches. x staged padded to 8 floats/step (4 u64 pairs).
    __shared__ __align__(16) u64 xs[2][TCHUNK * 4];                      // 2 KB
    __shared__ __align__(16) unsigned short spk[2][TCHUNK][SPK_STRIDE];  // 9 KB

    const int w    = threadIdx.x >> 5;
    const int lane = threadIdx.x & 31;
    const int pair = w >> 1;          // batch within block
    const int half = w & 1;           // h-half owned by this warp
    const int b    = blockIdx.x * 2 + pair;

    const int h = half * 32 + lane;   // this lane's hidden unit

    // --- W1 row packed over input pairs (bias folded into accumulator) ---
    u64 w1p[4];
#pragma unroll
    for (int k = 0; k < 3; k++)
        w1p[k] = pack2(W1[h * I_ + 2 * k], W1[h * I_ + 2 * k + 1]);
    w1p[3] = pack2(W1[h * I_ + 6], 0.0f);
    const u64 b1p = pack2(b1[h], 0.0f);

    // --- B fragments for HMMA (n8k16 col-major), W2 hi+lo fp16 split ---
    u32 bhi[4][2], blo[4][2];
    {
        const int o  = lane >> 2;
        const int kp = (lane & 3) * 2;
#pragma unroll
        for (int kt = 0; kt < 4; kt++) {
#pragma unroll
            for (int hh = 0; hh < 2; hh++) {
                const int k = kt * 16 + hh * 8 + kp;
                float wa = W2[o * H_ + k], wb = W2[o * H_ + k + 1];
                __half ha = __float2half_rn(wa);
                __half hb = __float2half_rn(wb);
                __half la = __float2half_rn(wa - __half2float(ha));
                __half lb = __float2half_rn(wb - __half2float(hb));
                __half2 vh = __halves2half2(ha, hb);
                __half2 vl = __halves2half2(la, lb);
                bhi[kt][hh] = *reinterpret_cast<u32*>(&vh);
                blo[kt][hh] = *reinterpret_cast<u32*>(&vl);
            }
        }
    }
    const float bi0 = b2[2 * (lane & 3)];
    const float bi1 = b2[2 * (lane & 3) + 1];

    // --- initial membrane + initial reset ---
    float mem = hs[(size_t)b * H_ + h];
    float s   = (mem > THRESH) ? 1.0f : 0.0f;

    const float* xb = x    + (size_t)b * T_ * I_;
    float*       nh = newh + (size_t)b * T_ * H_ + h;
    float*       ob = out  + (size_t)b * T_ * O_;

    const u32 spk_base = (u32)__cvta_generic_to_shared(&spk[pair][0][0]);
    const u32 lm_addr0 = spk_base + (u32)(lane & 15) * (SPK_STRIDE * 2)
                                  + (u32)(lane >> 4) * 16
                                  + (u32)half * 16 * (SPK_STRIDE * 2);

    for (int c0 = 0; c0 < T_; c0 += TCHUNK) {
        // ---- stage x chunk (warp half==0 of each pair; lane = timestep) ----
        if (half == 0) {
            const float* src = xb + (size_t)(c0 + lane) * I_;
            float v0 = __ldcs(src + 0), v1 = __ldcs(src + 1);
            float v2 = __ldcs(src + 2), v3 = __ldcs(src + 3);
            float v4 = __ldcs(src + 4), v5 = __ldcs(src + 5);
            float v6 = __ldcs(src + 6);
            ulonglong2 lo, hi;
            lo.x = pack2(v0, v1); lo.y = pack2(v2, v3);
            hi.x = pack2(v4, v5); hi.y = pack2(v6, 0.0f);
            *reinterpret_cast<ulonglong2*>(&xs[pair][lane * 4])     = lo;
            *reinterpret_cast<ulonglong2*>(&xs[pair][lane * 4 + 2]) = hi;
        }
        __syncthreads();

        // ---- phase 1: recurrence over 32 steps ----
#pragma unroll 4
        for (int tt = 0; tt < TCHUNK; tt++) {
            const int t = c0 + tt;
            const ulonglong2 xlo = *reinterpret_cast<const ulonglong2*>(&xs[pair][tt * 4]);
            const ulonglong2 xhi = *reinterpret_cast<const ulonglong2*>(&xs[pair][tt * 4 + 2]);

            u64 aa = fma2(xlo.x, w1p[0],
                     fma2(xlo.y, w1p[1],
                     fma2(xhi.x, w1p[2],
                     fma2(xhi.y, w1p[3], b1p))));
            float a0, a1; unpack2(aa, a0, a1);
            const float cur = a0 + a1;

            mem = fmaf(BETA, mem, cur) - s;

            __stcs(nh + (size_t)t * H_, mem);

            const bool fire = (mem > THRESH);
            s = fire ? 1.0f : 0.0f;
            spk[pair][tt][h] = fire ? (unsigned short)0x3C00 : (unsigned short)0;
        }
        __syncthreads();

        // ---- phase 2: outputs, m-tile split across the warp pair ----
        {
            float d0 = bi0, d1 = bi1, d2 = bi0, d3 = bi1;
#pragma unroll
            for (int kt = 0; kt < 4; kt++) {
                u32 a0, a1, a2, a3;
                ldsm_x4(a0, a1, a2, a3, lm_addr0 + (u32)(kt * 32));
                mma16816(d0, d1, d2, d3, a0, a1, a2, a3, bhi[kt][0], bhi[kt][1]);
                mma16816(d0, d1, d2, d3, a0, a1, a2, a3, blo[kt][0], blo[kt][1]);
            }
            const int row = half * 16 + (lane >> 2);
            const int col = 2 * (lane & 3);
            __stcs(reinterpret_cast<float2*>(ob + (size_t)(c0 + row) * O_ + col),
                   make_float2(d0, d1));
            __stcs(reinterpret_cast<float2*>(ob + (size_t)(c0 + row + 8) * O_ + col),
                   make_float2(d2, d3));
        }
        __syncthreads();
    }
}

extern "C" void kernel_launch(void* const* d_in, const int* in_sizes, int n_in,
                              void* d_out, int out_size)
{
    const float* x  = (const float*)d_in[0];
    const float* hs = (const float*)d_in[1];
    const float* W1 = (const float*)d_in[2];
    const float* b1 = (const float*)d_in[3];
    const float* W2 = (const float*)d_in[4];
    const float* b2 = (const float*)d_in[5];

    const int B = in_sizes[1] / H_;

    float* out  = (float*)d_out;                       // (B,T,O)
    float* newh = (float*)d_out + (size_t)B * T_ * O_; // (B,T,H)

    const int blocks = B / 2;   // 2 batches per block
    snn_kernel<<<blocks, 128>>>(x, hs, W1, b1, W2, b2, out, newh, B);
}

// round 9
// speedup vs baseline: 1.2103x; 1.2103x over previous
#include <cuda_runtime.h>
#include <cuda_fp16.h>

// SNN: B=4096, T=256, I=7, H=64, O=8
// 1 batch/warp, 2 hidden units/lane (R6 base). R8: newh stores go through a
// smem tile + cp.async.bulk (4KB contiguous per 16-step chunk) instead of
// per-step STG.64 — removes global-store backpressure from the warps and
// gives the DRAM perfectly sequential write bursts.

#define THRESH 1.0f
#define BETA 0.8f

typedef unsigned long long u64;
typedef unsigned int u32;

constexpr int T_ = 256;
constexpr int I_ = 7;
constexpr int H_ = 64;
constexpr int O_ = 8;
constexpr int WPB = 4;
constexpr int TCHUNK = 16;
constexpr int SPK_STRIDE = 72;   // halves per spike row (64 + 8 pad) = 144B

__device__ __forceinline__ u64 pack2(float lo, float hi) {
    u64 r; asm("mov.b64 %0, {%1, %2};" : "=l"(r) : "f"(lo), "f"(hi)); return r;
}
__device__ __forceinline__ void unpack2(u64 v, float& lo, float& hi) {
    asm("mov.b64 {%0, %1}, %2;" : "=f"(lo), "=f"(hi) : "l"(v));
}
__device__ __forceinline__ u64 fma2(u64 a, u64 b, u64 c) {
    u64 d; asm("fma.rn.f32x2 %0, %1, %2, %3;" : "=l"(d) : "l"(a), "l"(b), "l"(c)); return d;
}
__device__ __forceinline__ u32 cvt_f16x2(float lo, float hi) {
    u32 r; asm("cvt.rn.f16x2.f32 %0, %1, %2;" : "=r"(r) : "f"(hi), "f"(lo)); return r;
}
__device__ __forceinline__ void ldsm_x4(u32& r0, u32& r1, u32& r2, u32& r3, u32 addr) {
    asm volatile("ldmatrix.sync.aligned.m8n8.x4.shared.b16 {%0,%1,%2,%3}, [%4];"
                 : "=r"(r0), "=r"(r1), "=r"(r2), "=r"(r3) : "r"(addr));
}
__device__ __forceinline__ void mma16816(float& c0, float& c1, float& c2, float& c3,
                                         u32 a0, u32 a1, u32 a2, u32 a3,
                                         u32 b0, u32 b1) {
    asm volatile("mma.sync.aligned.m16n8k16.row.col.f32.f16.f16.f32 "
                 "{%0,%1,%2,%3},{%4,%5,%6,%7},{%8,%9},{%0,%1,%2,%3};"
                 : "+f"(c0), "+f"(c1), "+f"(c2), "+f"(c3)
                 : "r"(a0), "r"(a1), "r"(a2), "r"(a3), "r"(b0), "r"(b1));
}

__global__ __launch_bounds__(WPB * 32, 7)
void snn_kernel(const float* __restrict__ x,
                const float* __restrict__ hs,
                const float* __restrict__ W1,
                const float* __restrict__ b1,
                const float* __restrict__ W2,
                const float* __restrict__ b2,
                float* __restrict__ out,     // (B,T,8)
                float* __restrict__ newh,    // (B,T,64)
                int B)
{
    __shared__ __align__(16) u64 xs[WPB][TCHUNK * 4];                     // 2 KB
    __shared__ __align__(16) unsigned short spk[WPB][TCHUNK][SPK_STRIDE]; // 9 KB
    __shared__ __align__(16) float membuf[WPB][TCHUNK][H_];               // 16 KB

    const int w    = threadIdx.x >> 5;
    const int lane = threadIdx.x & 31;
    const int b    = blockIdx.x * WPB + w;
    if (b >= B) return;

    const int h0 = 2 * lane;

    // --- W1 packed over input pairs (bias folded into accumulator init) ---
    u64 w1a[4], w1b[4];
#pragma unroll
    for (int k = 0; k < 3; k++) {
        w1a[k] = pack2(W1[h0 * I_ + 2 * k],       W1[h0 * I_ + 2 * k + 1]);
        w1b[k] = pack2(W1[(h0 + 1) * I_ + 2 * k], W1[(h0 + 1) * I_ + 2 * k + 1]);
    }
    w1a[3] = pack2(W1[h0 * I_ + 6], 0.0f);
    w1b[3] = pack2(W1[(h0 + 1) * I_ + 6], 0.0f);
    const u64 b1a = pack2(b1[h0], 0.0f);
    const u64 b1b = pack2(b1[h0 + 1], 0.0f);

    // --- B fragments for HMMA (n8k16 col-major), W2 hi+lo fp16 split ---
    u32 bhi[4][2], blo[4][2];
    {
        const int o  = lane >> 2;
        const int kp = (lane & 3) * 2;
#pragma unroll
        for (int kt = 0; kt < 4; kt++) {
#pragma unroll
            for (int half = 0; half < 2; half++) {
                const int k = kt * 16 + half * 8 + kp;
                float wa = W2[o * H_ + k], wb = W2[o * H_ + k + 1];
                __half ha = __float2half_rn(wa);
                __half hb = __float2half_rn(wb);
                __half la = __float2half_rn(wa - __half2float(ha));
                __half lb = __float2half_rn(wb - __half2float(hb));
                __half2 vh = __halves2half2(ha, hb);
                __half2 vl = __halves2half2(la, lb);
                bhi[kt][half] = *reinterpret_cast<u32*>(&vh);
                blo[kt][half] = *reinterpret_cast<u32*>(&vl);
            }
        }
    }
    const float bi0 = b2[2 * (lane & 3)];
    const float bi1 = b2[2 * (lane & 3) + 1];

    // --- initial membrane + initial reset ---
    const float2 m2 = *reinterpret_cast<const float2*>(hs + (size_t)b * H_ + h0);
    float mem0 = m2.x, mem1 = m2.y;
    float s0 = (mem0 > THRESH) ? 1.0f : 0.0f;
    float s1 = (mem1 > THRESH) ? 1.0f : 0.0f;

    const float* xb = x    + (size_t)b * T_ * I_;
    float*       nh = newh + (size_t)b * T_ * H_;   // chunk-contiguous dst
    float*       ob = out  + (size_t)b * T_ * O_;

    const u32 spk_base = (u32)__cvta_generic_to_shared(&spk[w][0][0]);
    const u32 lm_addr0 = spk_base + (u32)(lane & 15) * (SPK_STRIDE * 2)
                                  + (u32)(lane >> 4) * 16;
    const u32 mb_base = (u32)__cvta_generic_to_shared(&membuf[w][0][0]);

    for (int c0 = 0; c0 < T_; c0 += TCHUNK) {
        // wait for previous chunk's bulk store to finish reading membuf
        if (lane == 0)
            asm volatile("cp.async.bulk.wait_group.read 0;" ::: "memory");
        __syncwarp();

        // ---- stage x chunk: lanes 0-15 load their timestep's 7 floats ----
        if (lane < TCHUNK) {
            const float* src = xb + (size_t)(c0 + lane) * I_;
            float v0 = __ldcs(src + 0), v1 = __ldcs(src + 1);
            float v2 = __ldcs(src + 2), v3 = __ldcs(src + 3);
            float v4 = __ldcs(src + 4), v5 = __ldcs(src + 5);
            float v6 = __ldcs(src + 6);
            ulonglong2 lo, hi;
            lo.x = pack2(v0, v1); lo.y = pack2(v2, v3);
            hi.x = pack2(v4, v5); hi.y = pack2(v6, 0.0f);
            *reinterpret_cast<ulonglong2*>(&xs[w][lane * 4])     = lo;
            *reinterpret_cast<ulonglong2*>(&xs[w][lane * 4 + 2]) = hi;
        }
        __syncwarp();

        // ---- phase 1: recurrence over 16 steps ----
#pragma unroll 4
        for (int tt = 0; tt < TCHUNK; tt++) {
            const ulonglong2 xlo = *reinterpret_cast<const ulonglong2*>(&xs[w][tt * 4]);
            const ulonglong2 xhi = *reinterpret_cast<const ulonglong2*>(&xs[w][tt * 4 + 2]);

            u64 aa = fma2(xlo.x, w1a[0],
                     fma2(xlo.y, w1a[1],
                     fma2(xhi.x, w1a[2],
                     fma2(xhi.y, w1a[3], b1a))));
            u64 ab = fma2(xlo.x, w1b[0],
                     fma2(xlo.y, w1b[1],
                     fma2(xhi.x, w1b[2],
                     fma2(xhi.y, w1b[3], b1b))));
            float a0, a1, c0f, c1f;
            unpack2(aa, a0, a1); c0f = a0 + a1;
            unpack2(ab, a0, a1); c1f = a0 + a1;

            mem0 = fmaf(BETA, mem0, c0f) - s0;
            mem1 = fmaf(BETA, mem1, c1f) - s1;

            // membrane -> smem tile (bulk-stored once per chunk)
            *reinterpret_cast<float2*>(&membuf[w][tt][h0]) =
                make_float2(mem0, mem1);

            s0 = (mem0 > THRESH) ? 1.0f : 0.0f;
            s1 = (mem1 > THRESH) ? 1.0f : 0.0f;

            *reinterpret_cast<u32*>(&spk[w][tt][2 * lane]) = cvt_f16x2(s0, s1);
        }
        __syncwarp();

        // ---- bulk store of newh chunk: 4KB contiguous, one issue ----
        asm volatile("fence.proxy.async.shared::cta;" ::: "memory");
        if (lane == 0) {
            asm volatile(
                "cp.async.bulk.global.shared::cta.bulk_group [%0], [%1], %2;"
                :: "l"(nh + (size_t)c0 * H_), "r"(mb_base),
                   "n"(TCHUNK * H_ * 4) : "memory");
            asm volatile("cp.async.bulk.commit_group;" ::: "memory");
        }

        // ---- phase 2: outputs for 16 steps via HMMA ----
        {
            float d0 = bi0, d1 = bi1, d2 = bi0, d3 = bi1;
#pragma unroll
            for (int kt = 0; kt < 4; kt++) {
                u32 a0, a1, a2, a3;
                ldsm_x4(a0, a1, a2, a3, lm_addr0 + (u32)(kt * 32));
                mma16816(d0, d1, d2, d3, a0, a1, a2, a3, bhi[kt][0], bhi[kt][1]);
                mma16816(d0, d1, d2, d3, a0, a1, a2, a3, blo[kt][0], blo[kt][1]);
            }
            const int row = lane >> 2;
            const int col = 2 * (lane & 3);
            __stcs(reinterpret_cast<float2*>(ob + (size_t)(c0 + row) * O_ + col),
                   make_float2(d0, d1));
            __stcs(reinterpret_cast<float2*>(ob + (size_t)(c0 + row + 8) * O_ + col),
                   make_float2(d2, d3));
        }
        __syncwarp();
    }
}

extern "C" void kernel_launch(void* const* d_in, const int* in_sizes, int n_in,
                              void* d_out, int out_size)
{
    const float* x  = (const float*)d_in[0];
    const float* hs = (const float*)d_in[1];
    const float* W1 = (const float*)d_in[2];
    const float* b1 = (const float*)d_in[3];
    const float* W2 = (const float*)d_in[4];
    const float* b2 = (const float*)d_in[5];

    const int B = in_sizes[1] / H_;

    float* out  = (float*)d_out;                       // (B,T,O)
    float* newh = (float*)d_out + (size_t)B * T_ * O_; // (B,T,H)

    const int blocks = (B + WPB - 1) / WPB;
    snn_kernel<<<blocks, WPB * 32>>>(x, hs, W1, b1, W2, b2, out, newh, B);
}

// round 10
// speedup vs baseline: 1.2400x; 1.0245x over previous
#include <cuda_runtime.h>
#include <cuda_fp16.h>

// SNN: B=4096, T=256, I=7, H=64, O=8
// 1 batch/warp, 2 hidden units/lane. Recurrence fp32; output matvec per
// 32-step chunk via HMMA m16n8k16 (spikes exact fp16, W2 hi+lo split).
// R9 (base R6): spike computed with FSET ((float)(cmp)) instead of
// FSETP+SEL -> loop-carried chain 21->8 cyc/step; recurrence unrolled x8.

#define THRESH 1.0f
#define BETA 0.8f

typedef unsigned long long u64;
typedef unsigned int u32;

constexpr int T_ = 256;
constexpr int I_ = 7;
constexpr int H_ = 64;
constexpr int O_ = 8;
constexpr int WPB = 4;
constexpr int TCHUNK = 32;
constexpr int SPK_STRIDE = 72;   // halves per spike row (64 + 8 pad) = 144B

__device__ __forceinline__ u64 pack2(float lo, float hi) {
    u64 r; asm("mov.b64 %0, {%1, %2};" : "=l"(r) : "f"(lo), "f"(hi)); return r;
}
__device__ __forceinline__ void unpack2(u64 v, float& lo, float& hi) {
    asm("mov.b64 {%0, %1}, %2;" : "=f"(lo), "=f"(hi) : "l"(v));
}
__device__ __forceinline__ u64 fma2(u64 a, u64 b, u64 c) {
    u64 d; asm("fma.rn.f32x2 %0, %1, %2, %3;" : "=l"(d) : "l"(a), "l"(b), "l"(c)); return d;
}
__device__ __forceinline__ u32 cvt_f16x2(float lo, float hi) {
    u32 r; asm("cvt.rn.f16x2.f32 %0, %1, %2;" : "=r"(r) : "f"(hi), "f"(lo)); return r;
}
__device__ __forceinline__ void ldsm_x4(u32& r0, u32& r1, u32& r2, u32& r3, u32 addr) {
    asm volatile("ldmatrix.sync.aligned.m8n8.x4.shared.b16 {%0,%1,%2,%3}, [%4];"
                 : "=r"(r0), "=r"(r1), "=r"(r2), "=r"(r3) : "r"(addr));
}
__device__ __forceinline__ void mma16816(float& c0, float& c1, float& c2, float& c3,
                                         u32 a0, u32 a1, u32 a2, u32 a3,
                                         u32 b0, u32 b1) {
    asm volatile("mma.sync.aligned.m16n8k16.row.col.f32.f16.f16.f32 "
                 "{%0,%1,%2,%3},{%4,%5,%6,%7},{%8,%9},{%0,%1,%2,%3};"
                 : "+f"(c0), "+f"(c1), "+f"(c2), "+f"(c3)
                 : "r"(a0), "r"(a1), "r"(a2), "r"(a3), "r"(b0), "r"(b1));
}

__global__ __launch_bounds__(WPB * 32, 8)
void snn_kernel(const float* __restrict__ x,
                const float* __restrict__ hs,
                const float* __restrict__ W1,
                const float* __restrict__ b1,
                const float* __restrict__ W2,
                const float* __restrict__ b2,
                float* __restrict__ out,     // (B,T,8)
                float* __restrict__ newh,    // (B,T,64)
                int B)
{
    // x staged plain, 8 floats (4 pairs) per timestep: u64[4] per step.
    __shared__ __align__(16) u64 xs[WPB][TCHUNK * 4];       // 4 KB
    __shared__ __align__(16) unsigned short spk[WPB][TCHUNK][SPK_STRIDE]; // 18 KB

    const int w    = threadIdx.x >> 5;
    const int lane = threadIdx.x & 31;
    const int b    = blockIdx.x * WPB + w;
    if (b >= B) return;

    const int h0 = 2 * lane;

    // --- W1 packed over input pairs (bias folded into accumulator init) ---
    u64 w1a[4], w1b[4];
#pragma unroll
    for (int k = 0; k < 3; k++) {
        w1a[k] = pack2(W1[h0 * I_ + 2 * k],       W1[h0 * I_ + 2 * k + 1]);
        w1b[k] = pack2(W1[(h0 + 1) * I_ + 2 * k], W1[(h0 + 1) * I_ + 2 * k + 1]);
    }
    w1a[3] = pack2(W1[h0 * I_ + 6], 0.0f);
    w1b[3] = pack2(W1[(h0 + 1) * I_ + 6], 0.0f);
    const u64 b1a = pack2(b1[h0], 0.0f);
    const u64 b1b = pack2(b1[h0 + 1], 0.0f);

    // --- B fragments for HMMA (n8k16 col-major), W2 hi+lo fp16 split ---
    u32 bhi[4][2], blo[4][2];
    {
        const int o  = lane >> 2;
        const int kp = (lane & 3) * 2;
#pragma unroll
        for (int kt = 0; kt < 4; kt++) {
#pragma unroll
            for (int half = 0; half < 2; half++) {
                const int k = kt * 16 + half * 8 + kp;
                float wa = W2[o * H_ + k], wb = W2[o * H_ + k + 1];
                __half ha = __float2half_rn(wa);
                __half hb = __float2half_rn(wb);
                __half la = __float2half_rn(wa - __half2float(ha));
                __half lb = __float2half_rn(wb - __half2float(hb));
                __half2 vh = __halves2half2(ha, hb);
                __half2 vl = __halves2half2(la, lb);
                bhi[kt][half] = *reinterpret_cast<u32*>(&vh);
                blo[kt][half] = *reinterpret_cast<u32*>(&vl);
            }
        }
    }
    const float bi0 = b2[2 * (lane & 3)];
    const float bi1 = b2[2 * (lane & 3) + 1];

    // --- initial membrane + initial reset ---
    const float2 m2 = *reinterpret_cast<const float2*>(hs + (size_t)b * H_ + h0);
    float mem0 = m2.x, mem1 = m2.y;
    float s0 = (float)(mem0 > THRESH);
    float s1 = (float)(mem1 > THRESH);

    const float* xb = x    + (size_t)b * T_ * I_;
    float*       nh = newh + (size_t)b * T_ * H_ + h0;
    float*       ob = out  + (size_t)b * T_ * O_;

    const u32 spk_base = (u32)__cvta_generic_to_shared(&spk[w][0][0]);
    const u32 lm_addr0 = spk_base + (u32)(lane & 15) * (SPK_STRIDE * 2)
                                  + (u32)(lane >> 4) * 16;

    for (int c0 = 0; c0 < T_; c0 += TCHUNK) {
        // ---- stage x chunk: lane tt loads its timestep's 7 floats,
        //      writes 2 STS.128 (pads i=7 with 0) ----
        {
            const float* src = xb + (size_t)(c0 + lane) * I_;
            float v0 = __ldcs(src + 0), v1 = __ldcs(src + 1);
            float v2 = __ldcs(src + 2), v3 = __ldcs(src + 3);
            float v4 = __ldcs(src + 4), v5 = __ldcs(src + 5);
            float v6 = __ldcs(src + 6);
            ulonglong2 lo, hi;
            lo.x = pack2(v0, v1); lo.y = pack2(v2, v3);
            hi.x = pack2(v4, v5); hi.y = pack2(v6, 0.0f);
            *reinterpret_cast<ulonglong2*>(&xs[w][lane * 4])     = lo;
            *reinterpret_cast<ulonglong2*>(&xs[w][lane * 4 + 2]) = hi;
        }
        __syncwarp();

        // ---- phase 1: recurrence over 32 steps, chain = FFMA+FSUB only ----
#pragma unroll 8
        for (int tt = 0; tt < TCHUNK; tt++) {
            const int t = c0 + tt;
            const ulonglong2 xlo = *reinterpret_cast<const ulonglong2*>(&xs[w][tt * 4]);
            const ulonglong2 xhi = *reinterpret_cast<const ulonglong2*>(&xs[w][tt * 4 + 2]);

            // cur for h0 / h1: 4 FFMA2 each, packed over input pairs
            u64 aa = fma2(xlo.x, w1a[0],
                     fma2(xlo.y, w1a[1],
                     fma2(xhi.x, w1a[2],
                     fma2(xhi.y, w1a[3], b1a))));
            u64 ab = fma2(xlo.x, w1b[0],
                     fma2(xlo.y, w1b[1],
                     fma2(xhi.x, w1b[2],
                     fma2(xhi.y, w1b[3], b1b))));
            float a0, a1, c0f, c1f;
            unpack2(aa, a0, a1); c0f = a0 + a1;
            unpack2(ab, a0, a1); c1f = a0 + a1;

            // mem' = (BETA*mem + cur) - spike_prev ; spike via FSET (4 cyc)
            mem0 = fmaf(BETA, mem0, c0f) - s0;
            mem1 = fmaf(BETA, mem1, c1f) - s1;

            __stcs(reinterpret_cast<float2*>(nh + (size_t)t * H_),
                   make_float2(mem0, mem1));

            s0 = (float)(mem0 > THRESH);
            s1 = (float)(mem1 > THRESH);

            *reinterpret_cast<u32*>(&spk[w][tt][2 * lane]) = cvt_f16x2(s0, s1);
        }
        __syncwarp();

        // ---- phase 2: outputs for 32 steps via HMMA ----
#pragma unroll
        for (int mt = 0; mt < 2; mt++) {
            float d0 = bi0, d1 = bi1, d2 = bi0, d3 = bi1;
#pragma unroll
            for (int kt = 0; kt < 4; kt++) {
                u32 a0, a1, a2, a3;
                ldsm_x4(a0, a1, a2, a3,
                        lm_addr0 + (u32)(mt * 16 * SPK_STRIDE * 2) + (u32)(kt * 32));
                mma16816(d0, d1, d2, d3, a0, a1, a2, a3, bhi[kt][0], bhi[kt][1]);
                mma16816(d0, d1, d2, d3, a0, a1, a2, a3, blo[kt][0], blo[kt][1]);
            }
            const int row = mt * 16 + (lane >> 2);
            const int col = 2 * (lane & 3);
            __stcs(reinterpret_cast<float2*>(ob + (size_t)(c0 + row) * O_ + col),
                   make_float2(d0, d1));
            __stcs(reinterpret_cast<float2*>(ob + (size_t)(c0 + row + 8) * O_ + col),
                   make_float2(d2, d3));
        }
        __syncwarp();
    }
}

extern "C" void kernel_launch(void* const* d_in, const int* in_sizes, int n_in,
                              void* d_out, int out_size)
{
    const float* x  = (const float*)d_in[0];
    const float* hs = (const float*)d_in[1];
    const float* W1 = (const float*)d_in[2];
    const float* b1 = (const float*)d_in[3];
    const float* W2 = (const float*)d_in[4];
    const float* b2 = (const float*)d_in[5];

    const int B = in_sizes[1] / H_;

    float* out  = (float*)d_out;                       // (B,T,O)
    float* newh = (float*)d_out + (size_t)B * T_ * O_; // (B,T,H)

    const int blocks = (B + WPB - 1) / WPB;
    snn_kernel<<<blocks, WPB * 32>>>(x, hs, W1, b1, W2, b2, out, newh, B);
}

// round 11
// speedup vs baseline: 1.2513x; 1.0091x over previous
#include <cuda_runtime.h>
#include <cuda_fp16.h>

// SNN: B=4096, T=256, I=7, H=64, O=8
// 1 batch/warp, 2 hidden units/lane. Recurrence fp32; output matvec per
// 32-step chunk via HMMA m16n8k16 (spikes exact fp16, W2 hi+lo split).
// R10 (base R9): x prefetched across chunks in registers (hides the DRAM
// round-trip at every chunk boundary); launch_bounds(128,6) for reg headroom
// so ptxas can hoist the per-step LDS pairs.

#define THRESH 1.0f
#define BETA 0.8f

typedef unsigned long long u64;
typedef unsigned int u32;

constexpr int T_ = 256;
constexpr int I_ = 7;
constexpr int H_ = 64;
constexpr int O_ = 8;
constexpr int WPB = 4;
constexpr int TCHUNK = 32;
constexpr int SPK_STRIDE = 72;   // halves per spike row (64 + 8 pad) = 144B

__device__ __forceinline__ u64 pack2(float lo, float hi) {
    u64 r; asm("mov.b64 %0, {%1, %2};" : "=l"(r) : "f"(lo), "f"(hi)); return r;
}
__device__ __forceinline__ void unpack2(u64 v, float& lo, float& hi) {
    asm("mov.b64 {%0, %1}, %2;" : "=f"(lo), "=f"(hi) : "l"(v));
}
__device__ __forceinline__ u64 fma2(u64 a, u64 b, u64 c) {
    u64 d; asm("fma.rn.f32x2 %0, %1, %2, %3;" : "=l"(d) : "l"(a), "l"(b), "l"(c)); return d;
}
__device__ __forceinline__ u32 cvt_f16x2(float lo, float hi) {
    u32 r; asm("cvt.rn.f16x2.f32 %0, %1, %2;" : "=r"(r) : "f"(hi), "f"(lo)); return r;
}
__device__ __forceinline__ void ldsm_x4(u32& r0, u32& r1, u32& r2, u32& r3, u32 addr) {
    asm volatile("ldmatrix.sync.aligned.m8n8.x4.shared.b16 {%0,%1,%2,%3}, [%4];"
                 : "=r"(r0), "=r"(r1), "=r"(r2), "=r"(r3) : "r"(addr));
}
__device__ __forceinline__ void mma16816(float& c0, float& c1, float& c2, float& c3,
                                         u32 a0, u32 a1, u32 a2, u32 a3,
                                         u32 b0, u32 b1) {
    asm volatile("mma.sync.aligned.m16n8k16.row.col.f32.f16.f16.f32 "
                 "{%0,%1,%2,%3},{%4,%5,%6,%7},{%8,%9},{%0,%1,%2,%3};"
                 : "+f"(c0), "+f"(c1), "+f"(c2), "+f"(c3)
                 : "r"(a0), "r"(a1), "r"(a2), "r"(a3), "r"(b0), "r"(b1));
}

__global__ __launch_bounds__(WPB * 32, 6)
void snn_kernel(const float* __restrict__ x,
                const float* __restrict__ hs,
                const float* __restrict__ W1,
                const float* __restrict__ b1,
                const float* __restrict__ W2,
                const float* __restrict__ b2,
                float* __restrict__ out,     // (B,T,8)
                float* __restrict__ newh,    // (B,T,64)
                int B)
{
    // x staged plain, 8 floats (4 pairs) per timestep: u64[4] per step.
    __shared__ __align__(16) u64 xs[WPB][TCHUNK * 4];       // 4 KB
    __shared__ __align__(16) unsigned short spk[WPB][TCHUNK][SPK_STRIDE]; // 18 KB

    const int w    = threadIdx.x >> 5;
    const int lane = threadIdx.x & 31;
    const int b    = blockIdx.x * WPB + w;
    if (b >= B) return;

    const int h0 = 2 * lane;

    // --- W1 packed over input pairs (bias folded into accumulator init) ---
    u64 w1a[4], w1b[4];
#pragma unroll
    for (int k = 0; k < 3; k++) {
        w1a[k] = pack2(W1[h0 * I_ + 2 * k],       W1[h0 * I_ + 2 * k + 1]);
        w1b[k] = pack2(W1[(h0 + 1) * I_ + 2 * k], W1[(h0 + 1) * I_ + 2 * k + 1]);
    }
    w1a[3] = pack2(W1[h0 * I_ + 6], 0.0f);
    w1b[3] = pack2(W1[(h0 + 1) * I_ + 6], 0.0f);
    const u64 b1a = pack2(b1[h0], 0.0f);
    const u64 b1b = pack2(b1[h0 + 1], 0.0f);

    // --- B fragments for HMMA (n8k16 col-major), W2 hi+lo fp16 split ---
    u32 bhi[4][2], blo[4][2];
    {
        const int o  = lane >> 2;
        const int kp = (lane & 3) * 2;
#pragma unroll
        for (int kt = 0; kt < 4; kt++) {
#pragma unroll
            for (int half = 0; half < 2; half++) {
                const int k = kt * 16 + half * 8 + kp;
                float wa = W2[o * H_ + k], wb = W2[o * H_ + k + 1];
                __half ha = __float2half_rn(wa);
                __half hb = __float2half_rn(wb);
                __half la = __float2half_rn(wa - __half2float(ha));
                __half lb = __float2half_rn(wb - __half2float(hb));
                __half2 vh = __halves2half2(ha, hb);
                __half2 vl = __halves2half2(la, lb);
                bhi[kt][half] = *reinterpret_cast<u32*>(&vh);
                blo[kt][half] = *reinterpret_cast<u32*>(&vl);
            }
        }
    }
    const float bi0 = b2[2 * (lane & 3)];
    const float bi1 = b2[2 * (lane & 3) + 1];

    // --- initial membrane + initial reset ---
    const float2 m2 = *reinterpret_cast<const float2*>(hs + (size_t)b * H_ + h0);
    float mem0 = m2.x, mem1 = m2.y;
    float s0 = (float)(mem0 > THRESH);
    float s1 = (float)(mem1 > THRESH);

    const float* xb = x    + (size_t)b * T_ * I_;
    float*       nh = newh + (size_t)b * T_ * H_ + h0;
    float*       ob = out  + (size_t)b * T_ * O_;

    const u32 spk_base = (u32)__cvta_generic_to_shared(&spk[w][0][0]);
    const u32 lm_addr0 = spk_base + (u32)(lane & 15) * (SPK_STRIDE * 2)
                                  + (u32)(lane >> 4) * 16;

    // ---- prefetch chunk 0's x rows into registers (lane = timestep) ----
    float p0, p1, p2, p3, p4, p5, p6;
    {
        const float* src = xb + (size_t)lane * I_;
        p0 = __ldcs(src + 0); p1 = __ldcs(src + 1); p2 = __ldcs(src + 2);
        p3 = __ldcs(src + 3); p4 = __ldcs(src + 4); p5 = __ldcs(src + 5);
        p6 = __ldcs(src + 6);
    }

    for (int c0 = 0; c0 < T_; c0 += TCHUNK) {
        // ---- stage prefetched x into smem: 2 STS.128 per lane ----
        {
            ulonglong2 lo, hi;
            lo.x = pack2(p0, p1); lo.y = pack2(p2, p3);
            hi.x = pack2(p4, p5); hi.y = pack2(p6, 0.0f);
            *reinterpret_cast<ulonglong2*>(&xs[w][lane * 4])     = lo;
            *reinterpret_cast<ulonglong2*>(&xs[w][lane * 4 + 2]) = hi;
        }
        __syncwarp();

        // ---- issue LDGs for the NEXT chunk now; they retire during the
        //      ~2.5K-cycle phase-1/2 body below (clamped on last chunk) ----
        {
            const int cnext = (c0 + TCHUNK < T_) ? (c0 + TCHUNK) : c0;
            const float* src = xb + (size_t)(cnext + lane) * I_;
            p0 = __ldcs(src + 0); p1 = __ldcs(src + 1); p2 = __ldcs(src + 2);
            p3 = __ldcs(src + 3); p4 = __ldcs(src + 4); p5 = __ldcs(src + 5);
            p6 = __ldcs(src + 6);
        }

        // ---- phase 1: recurrence over 32 steps, chain = FFMA+FSUB only ----
#pragma unroll 8
        for (int tt = 0; tt < TCHUNK; tt++) {
            const int t = c0 + tt;
            const ulonglong2 xlo = *reinterpret_cast<const ulonglong2*>(&xs[w][tt * 4]);
            const ulonglong2 xhi = *reinterpret_cast<const ulonglong2*>(&xs[w][tt * 4 + 2]);

            // cur for h0 / h1: 4 FFMA2 each, packed over input pairs
            u64 aa = fma2(xlo.x, w1a[0],
                     fma2(xlo.y, w1a[1],
                     fma2(xhi.x, w1a[2],
                     fma2(xhi.y, w1a[3], b1a))));
            u64 ab = fma2(xlo.x, w1b[0],
                     fma2(xlo.y, w1b[1],
                     fma2(xhi.x, w1b[2],
                     fma2(xhi.y, w1b[3], b1b))));
            float a0, a1, c0f, c1f;
            unpack2(aa, a0, a1); c0f = a0 + a1;
            unpack2(ab, a0, a1); c1f = a0 + a1;

            // mem' = (BETA*mem + cur) - spike_prev ; spike via FSET (4 cyc)
            mem0 = fmaf(BETA, mem0, c0f) - s0;
            mem1 = fmaf(BETA, mem1, c1f) - s1;

            __stcs(reinterpret_cast<float2*>(nh + (size_t)t * H_),
                   make_float2(mem0, mem1));

            s0 = (float)(mem0 > THRESH);
            s1 = (float)(mem1 > THRESH);

            *reinterpret_cast<u32*>(&spk[w][tt][2 * lane]) = cvt_f16x2(s0, s1);
        }
        __syncwarp();

        // ---- phase 2: outputs for 32 steps via HMMA ----
#pragma unroll
        for (int mt = 0; mt < 2; mt++) {
            float d0 = bi0, d1 = bi1, d2 = bi0, d3 = bi1;
#pragma unroll
            for (int kt = 0; kt < 4; kt++) {
                u32 a0, a1, a2, a3;
                ldsm_x4(a0, a1, a2, a3,
                        lm_addr0 + (u32)(mt * 16 * SPK_STRIDE * 2) + (u32)(kt * 32));
                mma16816(d0, d1, d2, d3, a0, a1, a2, a3, bhi[kt][0], bhi[kt][1]);
                mma16816(d0, d1, d2, d3, a0, a1, a2, a3, blo[kt][0], blo[kt][1]);
            }
            const int row = mt * 16 + (lane >> 2);
            const int col = 2 * (lane & 3);
            __stcs(reinterpret_cast<float2*>(ob + (size_t)(c0 + row) * O_ + col),
                   make_float2(d0, d1));
            __stcs(reinterpret_cast<float2*>(ob + (size_t)(c0 + row + 8) * O_ + col),
                   make_float2(d2, d3));
        }
        __syncwarp();
    }
}

extern "C" void kernel_launch(void* const* d_in, const int* in_sizes, int n_in,
                              void* d_out, int out_size)
{
    const float* x  = (const float*)d_in[0];
    const float* hs = (const float*)d_in[1];
    const float* W1 = (const float*)d_in[2];
    const float* b1 = (const float*)d_in[3];
    const float* W2 = (const float*)d_in[4];
    const float* b2 = (const float*)d_in[5];

    const int B = in_sizes[1] / H_;

    float* out  = (float*)d_out;                       // (B,T,O)
    float* newh = (float*)d_out + (size_t)B * T_ * O_; // (B,T,H)

    const int blocks = (B + WPB - 1) / WPB;
    snn_kernel<<<blocks, WPB * 32>>>(x, hs, W1, b1, W2, b2, out, newh, B);
}